// round 2
// baseline (speedup 1.0000x reference)
#include <cuda_runtime.h>
#include <cuda_bf16.h>

typedef unsigned long long ull;

#define D_DIM 2048
#define H1 256
#define H2 128
#define NB  384
#define MAX_B 8192

// Scratch (allocation-free rule: __device__ globals)
__device__ float g_scratch[MAX_B * NB];   // per-sample [a1(256) | g2(128)]
__device__ float g_u[H2];                 // u = Wo @ Wp
__device__ float g_w[H1];                 // w = W1^T @ Wp
__device__ float g_wpart[16][H1];
__device__ float g_W2T[H2 * H1];          // W2 transposed for coalesced backward reads

// ---- packed f32x2 helpers (sm_103a FFMA2) ----
__device__ __forceinline__ ull dup2(float x) {
    ull r; asm("mov.b64 %0, {%1, %1};" : "=l"(r) : "f"(x)); return r;
}
__device__ __forceinline__ void fma2(ull &d, ull a, ull b) {
    asm("fma.rn.f32x2 %0, %1, %2, %0;" : "+l"(d) : "l"(a), "l"(b));
}
__device__ __forceinline__ float2 unpack2(ull v) {
    float2 f; asm("mov.b64 {%0, %1}, %2;" : "=f"(f.x), "=f"(f.y) : "l"(v)); return f;
}

// ============================================================
// Kernel A: precompute u = Wo@Wp [128], partials of w = W1^T@Wp, W2^T
// grid = 160 blocks x 256 threads
// ============================================================
__global__ __launch_bounds__(256) void precompute_kernel(
    const float* __restrict__ W1, const float* __restrict__ W2,
    const float* __restrict__ Wo, const float* __restrict__ Wp)
{
    __shared__ float red[256];
    int tid = threadIdx.x, bk = blockIdx.x;
    if (bk < 128) {
        // u[bk] = dot(Wo[bk,:], Wp)
        float s = 0.f;
        for (int d = tid; d < D_DIM; d += 256)
            s += Wo[bk * D_DIM + d] * Wp[d];
        red[tid] = s; __syncthreads();
        for (int off = 128; off > 0; off >>= 1) {
            if (tid < off) red[tid] += red[tid + off];
            __syncthreads();
        }
        if (tid == 0) g_u[bk] = red[0];
    } else if (bk < 144) {
        // w partial over a 128-wide d-chunk (deterministic: no atomics)
        int c = bk - 128;
        float s = 0.f;
        #pragma unroll 4
        for (int q = 0; q < 128; q++) {
            int d = c * 128 + q;
            s += W1[(long long)d * H1 + tid] * Wp[d];  // coalesced across tid
        }
        g_wpart[c][tid] = s;
    } else {
        // transpose W2 [256,128] -> W2T [128,256]
        int base = (bk - 144) * 2048;
        for (int e = base + tid; e < base + 2048; e += 256) {
            int i = e >> 7, jq = e & 127;
            g_W2T[jq * H1 + i] = W2[e];
        }
    }
}

__global__ void reduce_w_kernel() {
    int i = threadIdx.x;
    float s = 0.f;
    #pragma unroll
    for (int c = 0; c < 16; c++) s += g_wpart[c][i];
    g_w[i] = s;
}

// ============================================================
// Kernel B: fused GEMM  S[b, 0:256]  = X[b,:] @ W1 + b1
//                       S[b, 256:384] = Wo @ X[b,:]
// grid = (B/64, 3), 256 threads. BM=64, BN=128, BK=16.
// Thread micro-tile 4x8 via packed FFMA2 (4x4 ull accumulators).
// ============================================================
__global__ __launch_bounds__(256) void gemm_kernel(
    const float* __restrict__ X, const float* __restrict__ W1,
    const float* __restrict__ b1, const float* __restrict__ Wo)
{
    __shared__ float Xs[16][64];
    __shared__ float Ws[16][128];

    int tid = threadIdx.x;
    int m0  = blockIdx.x * 64;
    int by  = blockIdx.y;          // 0,1 -> W1 cols; 2 -> Wo rows

    // loader indices
    int lxm = tid >> 2;            // 0..63 (row of X tile)
    int lxk = (tid & 3) << 2;      // 0,4,8,12
    int lwk = tid >> 4;            // 0..15 (W1 path: k)
    int lwn = (tid & 15) << 3;     // 0..120 (W1 path: n, step 8)
    int lon = tid >> 2;            // 0..63 (Wo path: n)
    int lok = (tid & 3) << 2;      // Wo path: k

    int tcol = tid & 15, trow = tid >> 4;
    int mB = trow << 2, nB = tcol << 3;

    ull acc[4][4];
    #pragma unroll
    for (int r = 0; r < 4; r++)
        #pragma unroll
        for (int c = 0; c < 4; c++) acc[r][c] = 0ull;

    const float* Xp = X + (long long)m0 * D_DIM;

    for (int k0 = 0; k0 < D_DIM; k0 += 16) {
        // stage global loads into regs (overlaps prior compute tail)
        float4 xv = *(const float4*)(Xp + (long long)lxm * D_DIM + k0 + lxk);
        float4 wa, wb;
        if (by < 2) {
            const float* wp = W1 + (long long)(k0 + lwk) * H1 + by * 128 + lwn;
            wa = *(const float4*)wp;
            wb = *(const float4*)(wp + 4);
        } else {
            const float* wp = Wo + (long long)lon * D_DIM + k0 + lok;
            wa = *(const float4*)wp;
            wb = *(const float4*)(wp + 64 * D_DIM);
        }
        __syncthreads();
        Xs[lxk + 0][lxm] = xv.x; Xs[lxk + 1][lxm] = xv.y;
        Xs[lxk + 2][lxm] = xv.z; Xs[lxk + 3][lxm] = xv.w;
        if (by < 2) {
            *(float4*)&Ws[lwk][lwn]     = wa;
            *(float4*)&Ws[lwk][lwn + 4] = wb;
        } else {
            Ws[lok + 0][lon] = wa.x; Ws[lok + 1][lon] = wa.y;
            Ws[lok + 2][lon] = wa.z; Ws[lok + 3][lon] = wa.w;
            Ws[lok + 0][lon + 64] = wb.x; Ws[lok + 1][lon + 64] = wb.y;
            Ws[lok + 2][lon + 64] = wb.z; Ws[lok + 3][lon + 64] = wb.w;
        }
        __syncthreads();

        #pragma unroll
        for (int kk = 0; kk < 16; kk++) {
            float4 x4 = *(const float4*)&Xs[kk][mB];
            ulonglong2 wA = *(const ulonglong2*)&Ws[kk][nB];
            ulonglong2 wB = *(const ulonglong2*)&Ws[kk][nB + 4];
            ull xd0 = dup2(x4.x), xd1 = dup2(x4.y), xd2 = dup2(x4.z), xd3 = dup2(x4.w);
            fma2(acc[0][0], xd0, wA.x); fma2(acc[0][1], xd0, wA.y);
            fma2(acc[0][2], xd0, wB.x); fma2(acc[0][3], xd0, wB.y);
            fma2(acc[1][0], xd1, wA.x); fma2(acc[1][1], xd1, wA.y);
            fma2(acc[1][2], xd1, wB.x); fma2(acc[1][3], xd1, wB.y);
            fma2(acc[2][0], xd2, wA.x); fma2(acc[2][1], xd2, wA.y);
            fma2(acc[2][2], xd2, wB.x); fma2(acc[2][3], xd2, wB.y);
            fma2(acc[3][0], xd3, wA.x); fma2(acc[3][1], xd3, wA.y);
            fma2(acc[3][2], xd3, wB.x); fma2(acc[3][3], xd3, wB.y);
        }
    }

    int ng = by * 128 + nB;
    #pragma unroll
    for (int r = 0; r < 4; r++) {
        long long row = (long long)(m0 + mB + r) * NB + ng;
        #pragma unroll
        for (int c = 0; c < 4; c++) {
            float2 v = unpack2(acc[r][c]);
            if (by < 2) {
                v.x += b1[ng + 2 * c];
                v.y += b1[ng + 2 * c + 1];
            }
            *(float2*)&g_scratch[row + 2 * c] = v;
        }
    }
}

// ============================================================
// Kernel C: per-sample epilogue, 8 samples per block, 128 threads.
// From a1[256], g2[128]:
//   th1 = m1*(a1-b1); h1 = relu(a1)
//   a2 = h1@W2+b2 ; t2 = th1@W2 ; m2 = a2>0
//   jx  = sum_j m2*t2[j]*u[j]
//   gh2 = m2*g2 ; g1 = W2@gh2 ; jtx = sum_i m1*g1[i]*w[i]
//   out = jx - jtx + bp
// ============================================================
__global__ __launch_bounds__(128) void epilogue_kernel(
    const float* __restrict__ b1, const float* __restrict__ W2,
    const float* __restrict__ b2, const float* __restrict__ bp,
    float* __restrict__ out)
{
    __shared__ float h1s[H1][8];
    __shared__ float th1s[H1][8];
    __shared__ float g2s[H2][8];
    __shared__ float gh2s[H2][8];
    __shared__ float wsum[4][8];

    int tid = threadIdx.x;
    int b0  = blockIdx.x * 8;

    // stage 1: load a1/g2 for 8 samples, apply relu / mask / bias-subtract
    for (int idx = tid; idx < 8 * H1; idx += 128) {
        int s = idx >> 8, i = idx & 255;
        float a = g_scratch[(b0 + s) * NB + i];
        bool m = a > 0.f;
        h1s[i][s]  = m ? a : 0.f;
        th1s[i][s] = m ? (a - b1[i]) : 0.f;   // t1 = a1 - b1
    }
    for (int idx = tid; idx < 8 * H2; idx += 128) {
        int s = idx >> 7, jq = idx & 127;
        g2s[jq][s] = g_scratch[(b0 + s) * NB + H1 + jq];
    }
    __syncthreads();

    // stage 2: thread j computes a2[j], t2[j] for all 8 samples (packed pairs)
    int j = tid;
    ull accA[4], accT[4];
    ull bd = dup2(b2[j]);
    #pragma unroll
    for (int p = 0; p < 4; p++) { accA[p] = bd; accT[p] = 0ull; }
    #pragma unroll 4
    for (int i = 0; i < H1; i++) {
        ull wd = dup2(W2[i * H2 + j]);               // coalesced across j
        const ull* hp = (const ull*)&h1s[i][0];      // broadcast, conflict-free
        const ull* tp = (const ull*)&th1s[i][0];
        #pragma unroll
        for (int p = 0; p < 4; p++) { fma2(accA[p], wd, hp[p]); fma2(accT[p], wd, tp[p]); }
    }
    float pr[8];
    float uj = g_u[j];
    #pragma unroll
    for (int p = 0; p < 4; p++) {
        float2 a2 = unpack2(accA[p]);
        float2 t2 = unpack2(accT[p]);
        bool ma = a2.x > 0.f, mb = a2.y > 0.f;
        pr[2 * p]     = ma ? t2.x * uj : 0.f;
        pr[2 * p + 1] = mb ? t2.y * uj : 0.f;
        gh2s[j][2 * p]     = ma ? g2s[j][2 * p] : 0.f;
        gh2s[j][2 * p + 1] = mb ? g2s[j][2 * p + 1] : 0.f;
    }
    __syncthreads();

    // stage 3: thread handles rows i0=tid, i1=tid+128 of g1 = W2 @ gh2
    int i0 = tid, i1 = tid + 128;
    ull gA[4] = {0,0,0,0}, gB[4] = {0,0,0,0};
    #pragma unroll 4
    for (int jj = 0; jj < H2; jj++) {
        ull w0 = dup2(g_W2T[jj * H1 + i0]);          // coalesced across tid
        ull w1 = dup2(g_W2T[jj * H1 + i1]);
        const ull* gp = (const ull*)&gh2s[jj][0];    // broadcast
        #pragma unroll
        for (int p = 0; p < 4; p++) { fma2(gA[p], w0, gp[p]); fma2(gB[p], w1, gp[p]); }
    }
    float wi0 = g_w[i0], wi1 = g_w[i1];
    #pragma unroll
    for (int p = 0; p < 4; p++) {
        float2 ga = unpack2(gA[p]);
        float2 gb = unpack2(gB[p]);
        float jt0 = 0.f, jt1 = 0.f;
        if (h1s[i0][2 * p] > 0.f)     jt0 += ga.x * wi0;
        if (h1s[i1][2 * p] > 0.f)     jt0 += gb.x * wi1;
        if (h1s[i0][2 * p + 1] > 0.f) jt1 += ga.y * wi0;
        if (h1s[i1][2 * p + 1] > 0.f) jt1 += gb.y * wi1;
        pr[2 * p]     -= jt0;
        pr[2 * p + 1] -= jt1;
    }

    // stage 4: reduce 128 partials per sample
    int lane = tid & 31, wpi = tid >> 5;
    #pragma unroll
    for (int s = 0; s < 8; s++) {
        float v = pr[s];
        #pragma unroll
        for (int off = 16; off > 0; off >>= 1)
            v += __shfl_xor_sync(0xffffffffu, v, off);
        if (lane == 0) wsum[wpi][s] = v;
    }
    __syncthreads();
    if (tid < 8) {
        out[b0 + tid] = wsum[0][tid] + wsum[1][tid] + wsum[2][tid] + wsum[3][tid] + bp[0];
    }
}

// ============================================================
// launch
// ============================================================
extern "C" void kernel_launch(void* const* d_in, const int* in_sizes, int n_in,
                              void* d_out, int out_size) {
    const float* x  = (const float*)d_in[0];
    const float* W1 = (const float*)d_in[1];
    const float* b1 = (const float*)d_in[2];
    const float* W2 = (const float*)d_in[3];
    const float* b2 = (const float*)d_in[4];
    const float* Wo = (const float*)d_in[5];
    // d_in[6] = bo : provably unused (cancels in J and J^T actions)
    const float* Wp = (const float*)d_in[7];
    const float* bp = (const float*)d_in[8];

    int B = in_sizes[0] / D_DIM;   // 8192

    precompute_kernel<<<160, 256>>>(W1, W2, Wo, Wp);
    reduce_w_kernel<<<1, 256>>>();

    dim3 gB(B / 64, 3);
    gemm_kernel<<<gB, 256>>>(x, W1, b1, Wo);

    epilogue_kernel<<<B / 8, 128>>>(b1, W2, b2, bp, (float*)d_out);
}

// round 7
// speedup vs baseline: 1.4134x; 1.4134x over previous
#include <cuda_runtime.h>
#include <cuda_bf16.h>
#include <cstdint>

typedef unsigned long long ull;

#define D_DIM 2048
#define H1 256
#define H2 128
#define NB  384
#define MAX_B 8192

static constexpr size_t A_PLANE = (size_t)MAX_B * D_DIM;
static constexpr size_t B_PLANE = (size_t)NB * D_DIM;

// ---------------- device scratch ----------------
__device__ uint16_t g_Abf[3 * A_PLANE];     // bf16 planes of X: h, m, l (for g2 path)
__device__ uint16_t g_Bbf[3 * B_PLANE];     // bf16 planes; only rows 256..383 (Wo) used
__device__ float    g_xT[(size_t)D_DIM * MAX_B];  // x transposed [k][m] (for a1 path)
__device__ float    g_scratch[(size_t)MAX_B * NB]; // [a1(256) | g2(128)]
__device__ float    g_u[H2];
__device__ float    g_w[H1];
__device__ float    g_wpart[16][H1];
__device__ float    g_W2T[H2 * H1];

// ---------------- helpers ----------------
__device__ __forceinline__ ull dup2(float x) {
    ull r; asm("mov.b64 %0, {%1, %1};" : "=l"(r) : "f"(x)); return r;
}
__device__ __forceinline__ void fma2(ull &d, ull a, ull b) {
    asm("fma.rn.f32x2 %0, %1, %2, %0;" : "+l"(d) : "l"(a), "l"(b));
}
__device__ __forceinline__ float2 unpack2(ull v) {
    float2 f; asm("mov.b64 {%0, %1}, %2;" : "=f"(f.x), "=f"(f.y) : "l"(v)); return f;
}
__device__ __forceinline__ void cpa16(uint32_t dst, const void* src) {
    asm volatile("cp.async.cg.shared.global [%0], [%1], 16;\n" :: "r"(dst), "l"(src));
}
__device__ __forceinline__ uint32_t s2u(const void* p) {
    uint32_t r; asm("{ .reg .u64 t; cvta.to.shared.u64 t, %1; cvt.u32.u64 %0, t; }" : "=r"(r) : "l"(p)); return r;
}
__device__ __forceinline__ uint32_t packbf(float hi, float lo) {
    uint32_t r; asm("cvt.rn.bf16x2.f32 %0, %1, %2;" : "=r"(r) : "f"(hi), "f"(lo)); return r;
}
__device__ __forceinline__ float bfhi(uint32_t v) { return __uint_as_float(v & 0xFFFF0000u); }
__device__ __forceinline__ float bflo(uint32_t v) { return __uint_as_float(v << 16); }

__device__ __forceinline__ void split3(float a, float b, uint32_t &h, uint32_t &m, uint32_t &l) {
    h = packbf(b, a);
    float ra = a - bflo(h), rb = b - bfhi(h);
    m = packbf(rb, ra);
    float sa = ra - bflo(m), sb = rb - bfhi(m);
    l = packbf(sb, sa);
}

__device__ __forceinline__ void mma16(float* c, const uint2* A, uint2 b) {
    asm volatile(
        "mma.sync.aligned.m16n8k16.row.col.f32.bf16.bf16.f32 "
        "{%0,%1,%2,%3}, {%4,%5,%6,%7}, {%8,%9}, {%0,%1,%2,%3};"
        : "+f"(c[0]), "+f"(c[1]), "+f"(c[2]), "+f"(c[3])
        : "r"(A[0].x), "r"(A[1].x), "r"(A[0].y), "r"(A[1].y), "r"(b.x), "r"(b.y));
}

// ============================================================
// prep_xT: transpose x [8192][2048] -> g_xT [2048][8192]. grid (64,256) x 256
// ============================================================
__global__ __launch_bounds__(256) void prep_xT(const float* __restrict__ X) {
    __shared__ float tile[32][33];
    int k0 = blockIdx.x * 32, m0 = blockIdx.y * 32;
    int tx = threadIdx.x & 31, ty = threadIdx.x >> 5;
    #pragma unroll
    for (int q = 0; q < 4; q++)
        tile[ty + 8 * q][tx] = X[(size_t)(m0 + ty + 8 * q) * D_DIM + k0 + tx];
    __syncthreads();
    #pragma unroll
    for (int q = 0; q < 4; q++)
        g_xT[(size_t)(k0 + ty + 8 * q) * MAX_B + m0 + tx] = tile[tx][ty + 8 * q];
}

// ============================================================
// prep_Abf: split X into 3 bf16 planes (for g2). grid 8192 x 256
// ============================================================
__global__ __launch_bounds__(256) void prep_Abf(const float* __restrict__ X) {
    size_t i = ((size_t)blockIdx.x * 256 + threadIdx.x) * 8;
    float4 v0 = *(const float4*)(X + i);
    float4 v1 = *(const float4*)(X + i + 4);
    uint32_t h[4], m[4], l[4];
    split3(v0.x, v0.y, h[0], m[0], l[0]);
    split3(v0.z, v0.w, h[1], m[1], l[1]);
    split3(v1.x, v1.y, h[2], m[2], l[2]);
    split3(v1.z, v1.w, h[3], m[3], l[3]);
    *(uint4*)(g_Abf + i)               = make_uint4(h[0], h[1], h[2], h[3]);
    *(uint4*)(g_Abf + A_PLANE + i)     = make_uint4(m[0], m[1], m[2], m[3]);
    *(uint4*)(g_Abf + 2 * A_PLANE + i) = make_uint4(l[0], l[1], l[2], l[3]);
}

// ============================================================
// prep_WoBf: Wo [128][2048] -> 3 bf16 planes at g_Bbf rows 256..383. grid 128 x 256
// ============================================================
__global__ __launch_bounds__(256) void prep_WoBf(const float* __restrict__ Wo) {
    size_t i = ((size_t)blockIdx.x * 256 + threadIdx.x) * 8;
    float4 v0 = *(const float4*)(Wo + i);
    float4 v1 = *(const float4*)(Wo + i + 4);
    uint32_t h[4], m[4], l[4];
    split3(v0.x, v0.y, h[0], m[0], l[0]);
    split3(v0.z, v0.w, h[1], m[1], l[1]);
    split3(v1.x, v1.y, h[2], m[2], l[2]);
    split3(v1.z, v1.w, h[3], m[3], l[3]);
    size_t off = (size_t)256 * D_DIM + i;
    *(uint4*)(g_Bbf + off)               = make_uint4(h[0], h[1], h[2], h[3]);
    *(uint4*)(g_Bbf + B_PLANE + off)     = make_uint4(m[0], m[1], m[2], m[3]);
    *(uint4*)(g_Bbf + 2 * B_PLANE + off) = make_uint4(l[0], l[1], l[2], l[3]);
}

// ============================================================
// precompute u = Wo@Wp, w = W1^T@Wp (partials), W2^T
// ============================================================
__global__ __launch_bounds__(256) void precompute_kernel(
    const float* __restrict__ W1, const float* __restrict__ W2,
    const float* __restrict__ Wo, const float* __restrict__ Wp)
{
    __shared__ float red[256];
    int tid = threadIdx.x, bk = blockIdx.x;
    if (bk < 128) {
        float s = 0.f;
        for (int d = tid; d < D_DIM; d += 256)
            s += Wo[bk * D_DIM + d] * Wp[d];
        red[tid] = s; __syncthreads();
        for (int off = 128; off > 0; off >>= 1) {
            if (tid < off) red[tid] += red[tid + off];
            __syncthreads();
        }
        if (tid == 0) g_u[bk] = red[0];
    } else if (bk < 144) {
        int c = bk - 128;
        float s = 0.f;
        #pragma unroll 4
        for (int q = 0; q < 128; q++) {
            int d = c * 128 + q;
            s += W1[(long long)d * H1 + tid] * Wp[d];
        }
        g_wpart[c][tid] = s;
    } else {
        int base = (bk - 144) * 2048;
        for (int e = base + tid; e < base + 2048; e += 256) {
            int i = e >> 7, jq = e & 127;
            g_W2T[jq * H1 + i] = W2[e];
        }
    }
}

__global__ void reduce_w_kernel() {
    int i = threadIdx.x;
    float s = 0.f;
    #pragma unroll
    for (int c = 0; c < 16; c++) s += g_wpart[c][i];
    g_w[i] = s;
}

// ============================================================
// gemm_a1: a1[m][n] = sum_k x[m][k] W1[k][n] + b1[n]
//   FFMA2, single fp32 accumulator per output, k strictly ascending
//   => bit-identical rounding to the round-2 passing kernel.
//   CTA 128x128, 256 thr (8 warps m64 x n32), 8x8 microtile, 4-stage cp.async.
//   grid (64, 2)
// ============================================================
#define AM 128
#define AN 128
#define AK 16
static constexpr int A_STG_B = (AM * AK + AN * AK) * 4;   // 16384
static constexpr int A_BOFF  = AM * AK * 4;               // 8192
static constexpr int A_SMEM  = 4 * A_STG_B;               // 65536

__device__ __forceinline__ void a1_load(uint32_t sb, int s, const float* __restrict__ W1,
                                        int m0, int n0, int k0, int tid) {
    uint32_t base = sb + s * A_STG_B;
    #pragma unroll
    for (int q = 0; q < 2; q++) {
        int idx = q * 256 + tid;
        int kk = idx >> 5, seg = idx & 31;
        cpa16(base + kk * 512 + seg * 16,
              g_xT + (size_t)(k0 + kk) * MAX_B + m0 + seg * 4);
    }
    #pragma unroll
    for (int q = 0; q < 2; q++) {
        int idx = q * 256 + tid;
        int kk = idx >> 5, seg = idx & 31;
        cpa16(base + A_BOFF + kk * 512 + seg * 16,
              W1 + (size_t)(k0 + kk) * H1 + n0 + seg * 4);
    }
    asm volatile("cp.async.commit_group;" ::: "memory");
}

__global__ __launch_bounds__(256, 1) void gemm_a1(const float* __restrict__ W1,
                                                  const float* __restrict__ b1) {
    extern __shared__ char smem[];
    uint32_t sb = s2u(smem);
    int tid = threadIdx.x, wid = tid >> 5, lid = tid & 31;
    int m0 = blockIdx.x * AM, n0 = blockIdx.y * AN;
    int wm = (wid & 1) * 64, wn = (wid >> 1) * 32;
    int r = lid >> 2, cg = lid & 3;

    ull acc[2][4][4];
    #pragma unroll
    for (int h = 0; h < 2; h++)
        #pragma unroll
        for (int b = 0; b < 4; b++)
            #pragma unroll
            for (int j = 0; j < 4; j++) acc[h][b][j] = 0ull;

    a1_load(sb, 0, W1, m0, n0, 0,      tid);
    a1_load(sb, 1, W1, m0, n0, AK,     tid);
    a1_load(sb, 2, W1, m0, n0, 2 * AK, tid);

    const int NITER = D_DIM / AK;   // 128
    for (int i = 0; i < NITER; i++) {
        int s = i & 3;
        asm volatile("cp.async.wait_group %0;" :: "n"(2) : "memory");
        __syncthreads();
        if (i + 3 < NITER) a1_load(sb, (i + 3) & 3, W1, m0, n0, (i + 3) * AK, tid);
        else asm volatile("cp.async.commit_group;" ::: "memory");

        const char* stg = smem + s * A_STG_B;
        #pragma unroll
        for (int kk = 0; kk < AK; kk++) {
            float4 a0  = *(const float4*)(stg + kk * 512 + (wm + 4 * r) * 4);
            float4 a1v = *(const float4*)(stg + kk * 512 + (wm + 32 + 4 * r) * 4);
            ulonglong2 bA = *(const ulonglong2*)(stg + A_BOFF + kk * 512 + (wn + 4 * cg) * 4);
            ulonglong2 bB = *(const ulonglong2*)(stg + A_BOFF + kk * 512 + (wn + 16 + 4 * cg) * 4);
            ull ad0[4] = { dup2(a0.x),  dup2(a0.y),  dup2(a0.z),  dup2(a0.w)  };
            ull ad1[4] = { dup2(a1v.x), dup2(a1v.y), dup2(a1v.z), dup2(a1v.w) };
            #pragma unroll
            for (int b = 0; b < 4; b++) {
                fma2(acc[0][b][0], ad0[b], bA.x); fma2(acc[0][b][1], ad0[b], bA.y);
                fma2(acc[0][b][2], ad0[b], bB.x); fma2(acc[0][b][3], ad0[b], bB.y);
                fma2(acc[1][b][0], ad1[b], bA.x); fma2(acc[1][b][1], ad1[b], bA.y);
                fma2(acc[1][b][2], ad1[b], bB.x); fma2(acc[1][b][3], ad1[b], bB.y);
            }
        }
    }

    #pragma unroll
    for (int h = 0; h < 2; h++)
        #pragma unroll
        for (int b = 0; b < 4; b++) {
            size_t M = (size_t)(m0 + wm + h * 32 + 4 * r + b);
            float* dst = g_scratch + M * NB + n0 + wn;
            #pragma unroll
            for (int j = 0; j < 4; j++) {
                int nc = (j >> 1) * 16 + 4 * cg + (j & 1) * 2;
                float2 v = unpack2(acc[h][b][j]);
                v.x += b1[n0 + wn + nc];
                v.y += b1[n0 + wn + nc + 1];
                *(float2*)(dst + nc) = v;
            }
        }
}

// ============================================================
// gemm_g2: g2[m][j] = sum_k x[m][k] Wo[j][k]  (linear path, bf16 6-product)
//   CTA BM=64 x BN=128 (all Wo rows), 128 thr, 4-stage. grid (B/64)
// ============================================================
#define BM 64
#define BN 128
#define KC 16
static constexpr int GA_STG  = 3 * BM * KC * 2;           // 6144
static constexpr int GB_OFF  = GA_STG;
static constexpr int G_STG   = GA_STG + 3 * BN * KC * 2;  // 18432
static constexpr int G_SMEM  = 4 * G_STG;                 // 73728

__device__ __forceinline__ void g2_load(uint32_t sb, int s, int m0, int k0, int tid) {
    uint32_t base = sb + s * G_STG;
    #pragma unroll
    for (int q = 0; q < 3; q++) {
        int i = q * 128 + tid;
        int plane = i >> 7, rem = i & 127, row = rem >> 1, half = rem & 1;
        cpa16(base + plane * 2048 + row * 32 + half * 16,
              g_Abf + (size_t)plane * A_PLANE + (size_t)(m0 + row) * D_DIM + k0 + half * 8);
    }
    #pragma unroll
    for (int q = 0; q < 6; q++) {
        int i = q * 128 + tid;
        int plane = i >> 8, rem = i & 255, row = rem >> 1, half = rem & 1;
        cpa16(base + GB_OFF + plane * 4096 + row * 32 + half * 16,
              g_Bbf + (size_t)plane * B_PLANE + (size_t)(256 + row) * D_DIM + k0 + half * 8);
    }
    asm volatile("cp.async.commit_group;" ::: "memory");
}

__global__ __launch_bounds__(128) void gemm_g2() {
    extern __shared__ char smem[];
    uint32_t sb = s2u(smem);
    int tid = threadIdx.x, wid = tid >> 5, lid = tid & 31;
    int m0 = blockIdx.x * BM;
    int warp_m = (wid & 1) * 32, warp_n = (wid >> 1) * 64;
    int rr = lid >> 2, cc = lid & 3;

    float c[2][8][4];
    #pragma unroll
    for (int mf = 0; mf < 2; mf++)
        #pragma unroll
        for (int nf = 0; nf < 8; nf++)
            #pragma unroll
            for (int q = 0; q < 4; q++) c[mf][nf][q] = 0.f;

    g2_load(sb, 0, m0, 0,      tid);
    g2_load(sb, 1, m0, KC,     tid);
    g2_load(sb, 2, m0, 2 * KC, tid);

    const int NITER = D_DIM / KC;
    for (int i = 0; i < NITER; i++) {
        int s = i & 3;
        asm volatile("cp.async.wait_group %0;" :: "n"(2) : "memory");
        __syncthreads();
        if (i + 3 < NITER) g2_load(sb, (i + 3) & 3, m0, (i + 3) * KC, tid);
        else asm volatile("cp.async.commit_group;" ::: "memory");

        const char* stg = smem + s * G_STG;
        uint2 Af[3][2][2];
        #pragma unroll
        for (int p = 0; p < 3; p++)
            #pragma unroll
            for (int mf = 0; mf < 2; mf++) {
                Af[p][mf][0] = *(const uint2*)(stg + p * 2048 + (warp_m + mf * 16 + rr)     * 32 + cc * 8);
                Af[p][mf][1] = *(const uint2*)(stg + p * 2048 + (warp_m + mf * 16 + 8 + rr) * 32 + cc * 8);
            }
        #pragma unroll
        for (int hh = 0; hh < 2; hh++) {
            uint2 Bf[3][4];
            #pragma unroll
            for (int p = 0; p < 3; p++)
                #pragma unroll
                for (int nf = 0; nf < 4; nf++)
                    Bf[p][nf] = *(const uint2*)(stg + GB_OFF + p * 4096 +
                                                (warp_n + (hh * 4 + nf) * 8 + rr) * 32 + cc * 8);
            #pragma unroll
            for (int nf = 0; nf < 4; nf++) {
                int nn = hh * 4 + nf;
                #pragma unroll
                for (int mf = 0; mf < 2; mf++) {
                    float* cp = c[mf][nn];
                    mma16(cp, Af[0][mf], Bf[0][nf]);
                    mma16(cp, Af[0][mf], Bf[1][nf]);
                    mma16(cp, Af[1][mf], Bf[0][nf]);
                    mma16(cp, Af[1][mf], Bf[1][nf]);
                    mma16(cp, Af[0][mf], Bf[2][nf]);
                    mma16(cp, Af[2][mf], Bf[0][nf]);
                }
            }
        }
    }

    #pragma unroll
    for (int mf = 0; mf < 2; mf++) {
        int mA = m0 + warp_m + mf * 16 + rr;
        #pragma unroll
        for (int nf = 0; nf < 8; nf++) {
            int n = 256 + warp_n + nf * 8 + 2 * cc;
            float2 v0 = { c[mf][nf][0], c[mf][nf][1] };
            float2 v1 = { c[mf][nf][2], c[mf][nf][3] };
            *(float2*)&g_scratch[(size_t)mA * NB + n]       = v0;
            *(float2*)&g_scratch[(size_t)(mA + 8) * NB + n] = v1;
        }
    }
}

// ============================================================
// Epilogue (byte-identical to the round-2 passing kernel)
// ============================================================
__global__ __launch_bounds__(128) void epilogue_kernel(
    const float* __restrict__ b1, const float* __restrict__ W2,
    const float* __restrict__ b2, const float* __restrict__ bp,
    float* __restrict__ out)
{
    __shared__ float h1s[H1][8];
    __shared__ float th1s[H1][8];
    __shared__ float g2s[H2][8];
    __shared__ float gh2s[H2][8];
    __shared__ float wsum[4][8];

    int tid = threadIdx.x;
    int b0  = blockIdx.x * 8;

    for (int idx = tid; idx < 8 * H1; idx += 128) {
        int s = idx >> 8, i = idx & 255;
        float a = g_scratch[(b0 + s) * NB + i];
        bool m = a > 0.f;
        h1s[i][s]  = m ? a : 0.f;
        th1s[i][s] = m ? (a - b1[i]) : 0.f;
    }
    for (int idx = tid; idx < 8 * H2; idx += 128) {
        int s = idx >> 7, jq = idx & 127;
        g2s[jq][s] = g_scratch[(b0 + s) * NB + H1 + jq];
    }
    __syncthreads();

    int j = tid;
    ull accA[4], accT[4];
    ull bd = dup2(b2[j]);
    #pragma unroll
    for (int p = 0; p < 4; p++) { accA[p] = bd; accT[p] = 0ull; }
    #pragma unroll 4
    for (int i = 0; i < H1; i++) {
        ull wd = dup2(W2[i * H2 + j]);
        const ull* hp = (const ull*)&h1s[i][0];
        const ull* tp = (const ull*)&th1s[i][0];
        #pragma unroll
        for (int p = 0; p < 4; p++) { fma2(accA[p], wd, hp[p]); fma2(accT[p], wd, tp[p]); }
    }
    float pr[8];
    float uj = g_u[j];
    #pragma unroll
    for (int p = 0; p < 4; p++) {
        float2 a2 = unpack2(accA[p]);
        float2 t2 = unpack2(accT[p]);
        bool ma = a2.x > 0.f, mb2 = a2.y > 0.f;
        pr[2 * p]     = ma  ? t2.x * uj : 0.f;
        pr[2 * p + 1] = mb2 ? t2.y * uj : 0.f;
        gh2s[j][2 * p]     = ma  ? g2s[j][2 * p]     : 0.f;
        gh2s[j][2 * p + 1] = mb2 ? g2s[j][2 * p + 1] : 0.f;
    }
    __syncthreads();

    int i0 = tid, i1 = tid + 128;
    ull gA2[4] = {0,0,0,0}, gB2[4] = {0,0,0,0};
    #pragma unroll 4
    for (int jj = 0; jj < H2; jj++) {
        ull w0 = dup2(g_W2T[jj * H1 + i0]);
        ull w1 = dup2(g_W2T[jj * H1 + i1]);
        const ull* gp = (const ull*)&gh2s[jj][0];
        #pragma unroll
        for (int p = 0; p < 4; p++) { fma2(gA2[p], w0, gp[p]); fma2(gB2[p], w1, gp[p]); }
    }
    float wi0 = g_w[i0], wi1 = g_w[i1];
    #pragma unroll
    for (int p = 0; p < 4; p++) {
        float2 ga = unpack2(gA2[p]);
        float2 gb = unpack2(gB2[p]);
        float jt0 = 0.f, jt1 = 0.f;
        if (h1s[i0][2 * p] > 0.f)     jt0 += ga.x * wi0;
        if (h1s[i1][2 * p] > 0.f)     jt0 += gb.x * wi1;
        if (h1s[i0][2 * p + 1] > 0.f) jt1 += ga.y * wi0;
        if (h1s[i1][2 * p + 1] > 0.f) jt1 += gb.y * wi1;
        pr[2 * p]     -= jt0;
        pr[2 * p + 1] -= jt1;
    }

    int lane = tid & 31, wpi = tid >> 5;
    #pragma unroll
    for (int s = 0; s < 8; s++) {
        float v = pr[s];
        #pragma unroll
        for (int off = 16; off > 0; off >>= 1)
            v += __shfl_xor_sync(0xffffffffu, v, off);
        if (lane == 0) wsum[wpi][s] = v;
    }
    __syncthreads();
    if (tid < 8) {
        out[b0 + tid] = wsum[0][tid] + wsum[1][tid] + wsum[2][tid] + wsum[3][tid] + bp[0];
    }
}

// ============================================================
// launch
// ============================================================
extern "C" void kernel_launch(void* const* d_in, const int* in_sizes, int n_in,
                              void* d_out, int out_size) {
    const float* x  = (const float*)d_in[0];
    const float* W1 = (const float*)d_in[1];
    const float* b1 = (const float*)d_in[2];
    const float* W2 = (const float*)d_in[3];
    const float* b2 = (const float*)d_in[4];
    const float* Wo = (const float*)d_in[5];
    const float* Wp = (const float*)d_in[7];
    const float* bp = (const float*)d_in[8];

    int B = in_sizes[0] / D_DIM;   // 8192

    cudaFuncSetAttribute(gemm_a1, cudaFuncAttributeMaxDynamicSharedMemorySize, A_SMEM);
    cudaFuncSetAttribute(gemm_g2, cudaFuncAttributeMaxDynamicSharedMemorySize, G_SMEM);

    prep_xT<<<dim3(64, 256), 256>>>(x);
    prep_Abf<<<(int)((size_t)B * D_DIM / 2048), 256>>>(x);
    prep_WoBf<<<128, 256>>>(Wo);
    precompute_kernel<<<160, 256>>>(W1, W2, Wo, Wp);
    reduce_w_kernel<<<1, 256>>>();

    gemm_a1<<<dim3(B / AM, 2), 256, A_SMEM>>>(W1, b1);
    gemm_g2<<<B / BM, 128, G_SMEM>>>();

    epilogue_kernel<<<B / 8, 128>>>(b1, W2, b2, bp, (float*)d_out);
}

// round 8
// speedup vs baseline: 1.5349x; 1.0859x over previous
#include <cuda_runtime.h>
#include <cuda_bf16.h>
#include <cstdint>

typedef unsigned long long ull;

#define D_DIM 2048
#define H1 256
#define H2 128
#define NB  384
#define MAX_B 8192

static constexpr size_t B_PLANE = (size_t)NB * D_DIM;

// ---------------- device scratch ----------------
__device__ uint16_t g_Bbf[3 * B_PLANE];            // bf16 planes; rows 256..383 (Wo) used
__device__ float    g_xT[(size_t)D_DIM * MAX_B];   // x transposed [k][m]
__device__ float    g_scratch[(size_t)MAX_B * NB]; // [a1(256) | g2(128)]
__device__ float    g_u[H2];
__device__ float    g_w[H1];
__device__ float    g_wpart[16][H1];
__device__ float    g_W2T[H2 * H1];

// ---------------- helpers ----------------
__device__ __forceinline__ ull dup2(float x) {
    ull r; asm("mov.b64 %0, {%1, %1};" : "=l"(r) : "f"(x)); return r;
}
__device__ __forceinline__ void fma2(ull &d, ull a, ull b) {
    asm("fma.rn.f32x2 %0, %1, %2, %0;" : "+l"(d) : "l"(a), "l"(b));
}
__device__ __forceinline__ float2 unpack2(ull v) {
    float2 f; asm("mov.b64 {%0, %1}, %2;" : "=f"(f.x), "=f"(f.y) : "l"(v)); return f;
}
__device__ __forceinline__ void cpa16(uint32_t dst, const void* src) {
    asm volatile("cp.async.cg.shared.global [%0], [%1], 16;\n" :: "r"(dst), "l"(src));
}
__device__ __forceinline__ uint32_t s2u(const void* p) {
    uint32_t r; asm("{ .reg .u64 t; cvta.to.shared.u64 t, %1; cvt.u32.u64 %0, t; }" : "=r"(r) : "l"(p)); return r;
}
__device__ __forceinline__ uint32_t packbf(float hi, float lo) {
    uint32_t r; asm("cvt.rn.bf16x2.f32 %0, %1, %2;" : "=r"(r) : "f"(hi), "f"(lo)); return r;
}
__device__ __forceinline__ float bfhi(uint32_t v) { return __uint_as_float(v & 0xFFFF0000u); }
__device__ __forceinline__ float bflo(uint32_t v) { return __uint_as_float(v << 16); }

__device__ __forceinline__ void split3(float a, float b, uint32_t &h, uint32_t &m, uint32_t &l) {
    h = packbf(b, a);
    float ra = a - bflo(h), rb = b - bfhi(h);
    m = packbf(rb, ra);
    float sa = ra - bflo(m), sb = rb - bfhi(m);
    l = packbf(sb, sa);
}

__device__ __forceinline__ void mma16(float* c, const uint2* A, uint2 b) {
    asm volatile(
        "mma.sync.aligned.m16n8k16.row.col.f32.bf16.bf16.f32 "
        "{%0,%1,%2,%3}, {%4,%5,%6,%7}, {%8,%9}, {%0,%1,%2,%3};"
        : "+f"(c[0]), "+f"(c[1]), "+f"(c[2]), "+f"(c[3])
        : "r"(A[0].x), "r"(A[1].x), "r"(A[0].y), "r"(A[1].y), "r"(b.x), "r"(b.y));
}

// ============================================================
// prep_xT: transpose x [8192][2048] -> g_xT [2048][8192]. grid (64,256) x 256
// ============================================================
__global__ __launch_bounds__(256) void prep_xT(const float* __restrict__ X) {
    __shared__ float tile[32][33];
    int k0 = blockIdx.x * 32, m0 = blockIdx.y * 32;
    int tx = threadIdx.x & 31, ty = threadIdx.x >> 5;
    #pragma unroll
    for (int q = 0; q < 4; q++)
        tile[ty + 8 * q][tx] = X[(size_t)(m0 + ty + 8 * q) * D_DIM + k0 + tx];
    __syncthreads();
    #pragma unroll
    for (int q = 0; q < 4; q++)
        g_xT[(size_t)(k0 + ty + 8 * q) * MAX_B + m0 + tx] = tile[tx][ty + 8 * q];
}

// ============================================================
// prep_misc: u = Wo@Wp (bk<128), wpart (bk<144), W2T (bk<160),
//            Wo bf16 planes (bk 160..287). grid 288 x 256
// ============================================================
__global__ __launch_bounds__(256) void prep_misc(
    const float* __restrict__ W1, const float* __restrict__ W2,
    const float* __restrict__ Wo, const float* __restrict__ Wp)
{
    __shared__ float red[256];
    int tid = threadIdx.x, bk = blockIdx.x;
    if (bk < 128) {
        float s = 0.f;
        #pragma unroll 4
        for (int d = tid; d < D_DIM; d += 256)
            s += Wo[bk * D_DIM + d] * Wp[d];
        red[tid] = s; __syncthreads();
        for (int off = 128; off > 0; off >>= 1) {
            if (tid < off) red[tid] += red[tid + off];
            __syncthreads();
        }
        if (tid == 0) g_u[bk] = red[0];
    } else if (bk < 144) {
        int c = bk - 128;
        float s = 0.f;
        #pragma unroll 4
        for (int q = 0; q < 128; q++) {
            int d = c * 128 + q;
            s += W1[(long long)d * H1 + tid] * Wp[d];
        }
        g_wpart[c][tid] = s;
    } else if (bk < 160) {
        int base = (bk - 144) * 2048;
        for (int e = base + tid; e < base + 2048; e += 256) {
            int i = e >> 7, jq = e & 127;
            g_W2T[jq * H1 + i] = W2[e];
        }
    } else {
        size_t i = ((size_t)(bk - 160) * 256 + tid) * 8;   // Wo [128 x 2048]
        float4 v0 = *(const float4*)(Wo + i);
        float4 v1 = *(const float4*)(Wo + i + 4);
        uint32_t h[4], m[4], l[4];
        split3(v0.x, v0.y, h[0], m[0], l[0]);
        split3(v0.z, v0.w, h[1], m[1], l[1]);
        split3(v1.x, v1.y, h[2], m[2], l[2]);
        split3(v1.z, v1.w, h[3], m[3], l[3]);
        size_t off = (size_t)256 * D_DIM + i;
        *(uint4*)(g_Bbf + off)               = make_uint4(h[0], h[1], h[2], h[3]);
        *(uint4*)(g_Bbf + B_PLANE + off)     = make_uint4(m[0], m[1], m[2], m[3]);
        *(uint4*)(g_Bbf + 2 * B_PLANE + off) = make_uint4(l[0], l[1], l[2], l[3]);
    }
}

__global__ void reduce_w_kernel() {
    int i = threadIdx.x;
    float s = 0.f;
    #pragma unroll
    for (int c = 0; c < 16; c++) s += g_wpart[c][i];
    g_w[i] = s;
}

// ============================================================
// gemm_a1: a1[m][n] = sum_k x[m][k] W1[k][n] + b1[n]
//   FFMA2, single fp32 accumulator per output, k strictly ascending
//   (rounding chain bit-identical to round-2/round-7 passing kernels).
//   CTA 128m x 64n, 128 thr (4 warps: warp 64m x 32n), 8x8 microtile,
//   4-stage cp.async. grid (64, 4) = 256 CTAs.
// ============================================================
#define AM 128
#define AN 64
#define AK 16
static constexpr int A_STG_B = (AM * AK + AN * AK) * 4;   // 12288
static constexpr int A_BOFF  = AM * AK * 4;               // 8192
static constexpr int A_SMEM  = 4 * A_STG_B;               // 49152

__device__ __forceinline__ void a1_load(uint32_t sb, int s, const float* __restrict__ W1,
                                        int m0, int n0, int k0, int tid) {
    uint32_t base = sb + s * A_STG_B;
    #pragma unroll
    for (int q = 0; q < 4; q++) {        // A: 128 m x 16 k = 512 float4
        int idx = q * 128 + tid;
        int kk = idx >> 5, seg = idx & 31;
        cpa16(base + kk * 512 + seg * 16,
              g_xT + (size_t)(k0 + kk) * MAX_B + m0 + seg * 4);
    }
    #pragma unroll
    for (int q = 0; q < 2; q++) {        // B: 64 n x 16 k = 256 float4
        int idx = q * 128 + tid;
        int kk = idx >> 4, seg = idx & 15;
        cpa16(base + A_BOFF + kk * 256 + seg * 16,
              W1 + (size_t)(k0 + kk) * H1 + n0 + seg * 4);
    }
    asm volatile("cp.async.commit_group;" ::: "memory");
}

__global__ __launch_bounds__(128) void gemm_a1(const float* __restrict__ W1,
                                               const float* __restrict__ b1) {
    extern __shared__ char smem[];
    uint32_t sb = s2u(smem);
    int tid = threadIdx.x, wid = tid >> 5, lid = tid & 31;
    int m0 = blockIdx.x * AM, n0 = blockIdx.y * AN;
    int wm = (wid & 1) * 64, wn = (wid >> 1) * 32;
    int r = lid >> 2, cg = lid & 3;

    ull acc[2][4][4];
    #pragma unroll
    for (int h = 0; h < 2; h++)
        #pragma unroll
        for (int b = 0; b < 4; b++)
            #pragma unroll
            for (int j = 0; j < 4; j++) acc[h][b][j] = 0ull;

    a1_load(sb, 0, W1, m0, n0, 0,      tid);
    a1_load(sb, 1, W1, m0, n0, AK,     tid);
    a1_load(sb, 2, W1, m0, n0, 2 * AK, tid);

    const int NITER = D_DIM / AK;   // 128
    for (int i = 0; i < NITER; i++) {
        int s = i & 3;
        asm volatile("cp.async.wait_group %0;" :: "n"(2) : "memory");
        __syncthreads();
        if (i + 3 < NITER) a1_load(sb, (i + 3) & 3, W1, m0, n0, (i + 3) * AK, tid);
        else asm volatile("cp.async.commit_group;" ::: "memory");

        const char* stg = smem + s * A_STG_B;
        #pragma unroll
        for (int kk = 0; kk < AK; kk++) {
            float4 a0  = *(const float4*)(stg + kk * 512 + (wm + 4 * r) * 4);
            float4 a1v = *(const float4*)(stg + kk * 512 + (wm + 32 + 4 * r) * 4);
            ulonglong2 bA = *(const ulonglong2*)(stg + A_BOFF + kk * 256 + (wn + 4 * cg) * 4);
            ulonglong2 bB = *(const ulonglong2*)(stg + A_BOFF + kk * 256 + (wn + 16 + 4 * cg) * 4);
            ull ad0[4] = { dup2(a0.x),  dup2(a0.y),  dup2(a0.z),  dup2(a0.w)  };
            ull ad1[4] = { dup2(a1v.x), dup2(a1v.y), dup2(a1v.z), dup2(a1v.w) };
            #pragma unroll
            for (int b = 0; b < 4; b++) {
                fma2(acc[0][b][0], ad0[b], bA.x); fma2(acc[0][b][1], ad0[b], bA.y);
                fma2(acc[0][b][2], ad0[b], bB.x); fma2(acc[0][b][3], ad0[b], bB.y);
                fma2(acc[1][b][0], ad1[b], bA.x); fma2(acc[1][b][1], ad1[b], bA.y);
                fma2(acc[1][b][2], ad1[b], bB.x); fma2(acc[1][b][3], ad1[b], bB.y);
            }
        }
    }

    #pragma unroll
    for (int h = 0; h < 2; h++)
        #pragma unroll
        for (int b = 0; b < 4; b++) {
            size_t M = (size_t)(m0 + wm + h * 32 + 4 * r + b);
            float* dst = g_scratch + M * NB + n0 + wn;
            #pragma unroll
            for (int j = 0; j < 4; j++) {
                int nc = (j >> 1) * 16 + 4 * cg + (j & 1) * 2;
                float2 v = unpack2(acc[h][b][j]);
                v.x += b1[n0 + wn + nc];
                v.y += b1[n0 + wn + nc + 1];
                *(float2*)(dst + nc) = v;
            }
        }
}

// ============================================================
// gemm_g2: g2[m][j] = sum_k x[m][k] Wo[j][k]  (linear path)
//   bf16 6-product; A (x) loaded fp32, split3 in registers (bit-identical
//   to the plane path). CTA 64m x 128n, 128 thr, 4-stage. grid B/64.
// ============================================================
#define BM 64
#define BN 128
#define KC 16
static constexpr int GB_OFF  = BM * KC * 4;               // 4096 (A fp32 stage)
static constexpr int G_STG   = GB_OFF + 3 * BN * KC * 2;  // 16384
static constexpr int G_SMEM  = 4 * G_STG;                 // 65536

__device__ __forceinline__ void g2_load(uint32_t sb, int s, const float* __restrict__ X,
                                        int m0, int k0, int tid) {
    uint32_t base = sb + s * G_STG;
    #pragma unroll
    for (int q = 0; q < 2; q++) {        // A: 64 rows x 64B = 256 float4
        int idx = q * 128 + tid;
        int row = idx >> 2, seg = idx & 3;
        cpa16(base + row * 64 + seg * 16,
              X + (size_t)(m0 + row) * D_DIM + k0 + seg * 4);
    }
    #pragma unroll
    for (int q = 0; q < 6; q++) {        // B: 3 planes x 128 rows x 32B
        int i = q * 128 + tid;
        int plane = i >> 8, rem = i & 255, row = rem >> 1, half = rem & 1;
        cpa16(base + GB_OFF + plane * 4096 + row * 32 + half * 16,
              g_Bbf + (size_t)plane * B_PLANE + (size_t)(256 + row) * D_DIM + k0 + half * 8);
    }
    asm volatile("cp.async.commit_group;" ::: "memory");
}

__global__ __launch_bounds__(128) void gemm_g2(const float* __restrict__ X) {
    extern __shared__ char smem[];
    uint32_t sb = s2u(smem);
    int tid = threadIdx.x, wid = tid >> 5, lid = tid & 31;
    int m0 = blockIdx.x * BM;
    int warp_m = (wid & 1) * 32, warp_n = (wid >> 1) * 64;
    int rr = lid >> 2, cc = lid & 3;

    float c[2][8][4];
    #pragma unroll
    for (int mf = 0; mf < 2; mf++)
        #pragma unroll
        for (int nf = 0; nf < 8; nf++)
            #pragma unroll
            for (int q = 0; q < 4; q++) c[mf][nf][q] = 0.f;

    g2_load(sb, 0, X, m0, 0,      tid);
    g2_load(sb, 1, X, m0, KC,     tid);
    g2_load(sb, 2, X, m0, 2 * KC, tid);

    const int NITER = D_DIM / KC;
    for (int i = 0; i < NITER; i++) {
        int s = i & 3;
        asm volatile("cp.async.wait_group %0;" :: "n"(2) : "memory");
        __syncthreads();
        if (i + 3 < NITER) g2_load(sb, (i + 3) & 3, X, m0, (i + 3) * KC, tid);
        else asm volatile("cp.async.commit_group;" ::: "memory");

        const char* stg = smem + s * G_STG;

        // A: load fp32, split in registers (same split3 => bit-identical)
        uint2 Af[3][2][2];
        #pragma unroll
        for (int mf = 0; mf < 2; mf++)
            #pragma unroll
            for (int j = 0; j < 2; j++) {
                float4 v = *(const float4*)(stg + (warp_m + mf * 16 + j * 8 + rr) * 64 + cc * 16);
                uint32_t h0, m0_, l0, h1, m1_, l1;
                split3(v.x, v.y, h0, m0_, l0);
                split3(v.z, v.w, h1, m1_, l1);
                Af[0][mf][j] = make_uint2(h0, h1);
                Af[1][mf][j] = make_uint2(m0_, m1_);
                Af[2][mf][j] = make_uint2(l0, l1);
            }

        #pragma unroll
        for (int hh = 0; hh < 2; hh++) {
            uint2 Bf[3][4];
            #pragma unroll
            for (int p = 0; p < 3; p++)
                #pragma unroll
                for (int nf = 0; nf < 4; nf++)
                    Bf[p][nf] = *(const uint2*)(stg + GB_OFF + p * 4096 +
                                                (warp_n + (hh * 4 + nf) * 8 + rr) * 32 + cc * 8);
            #pragma unroll
            for (int nf = 0; nf < 4; nf++) {
                int nn = hh * 4 + nf;
                #pragma unroll
                for (int mf = 0; mf < 2; mf++) {
                    float* cp = c[mf][nn];
                    mma16(cp, Af[0][mf], Bf[0][nf]);
                    mma16(cp, Af[0][mf], Bf[1][nf]);
                    mma16(cp, Af[1][mf], Bf[0][nf]);
                    mma16(cp, Af[1][mf], Bf[1][nf]);
                    mma16(cp, Af[0][mf], Bf[2][nf]);
                    mma16(cp, Af[2][mf], Bf[0][nf]);
                }
            }
        }
    }

    #pragma unroll
    for (int mf = 0; mf < 2; mf++) {
        int mA = m0 + warp_m + mf * 16 + rr;
        #pragma unroll
        for (int nf = 0; nf < 8; nf++) {
            int n = 256 + warp_n + nf * 8 + 2 * cc;
            float2 v0 = { c[mf][nf][0], c[mf][nf][1] };
            float2 v1 = { c[mf][nf][2], c[mf][nf][3] };
            *(float2*)&g_scratch[(size_t)mA * NB + n]       = v0;
            *(float2*)&g_scratch[(size_t)(mA + 8) * NB + n] = v1;
        }
    }
}

// ============================================================
// Epilogue: 16 samples/block, 128 threads. Same per-sample chains
// (thread<->j/i mapping, i/jj order, fma2 pairing) as the passing kernel.
// ============================================================
__global__ __launch_bounds__(128) void epilogue_kernel(
    const float* __restrict__ b1, const float* __restrict__ W2,
    const float* __restrict__ b2, const float* __restrict__ bp,
    float* __restrict__ out)
{
    __shared__ float h1s[H1][16];
    __shared__ float th1s[H1][16];
    __shared__ float gh2s[H2][16];
    __shared__ float wsum[4][16];

    int tid = threadIdx.x;
    int b0  = blockIdx.x * 16;

    for (int idx = tid; idx < 16 * H1; idx += 128) {
        int s = idx >> 8, i = idx & 255;
        float a = g_scratch[(size_t)(b0 + s) * NB + i];
        bool m = a > 0.f;
        h1s[i][s]  = m ? a : 0.f;
        th1s[i][s] = m ? (a - b1[i]) : 0.f;
    }
    __syncthreads();

    int j = tid;
    ull accA[8], accT[8];
    ull bd = dup2(b2[j]);
    #pragma unroll
    for (int p = 0; p < 8; p++) { accA[p] = bd; accT[p] = 0ull; }
    #pragma unroll 4
    for (int i = 0; i < H1; i++) {
        ull wd = dup2(W2[i * H2 + j]);
        const ull* hp = (const ull*)&h1s[i][0];
        const ull* tp = (const ull*)&th1s[i][0];
        #pragma unroll
        for (int p = 0; p < 8; p++) { fma2(accA[p], wd, hp[p]); fma2(accT[p], wd, tp[p]); }
    }
    float pr[16];
    float uj = g_u[j];
    #pragma unroll
    for (int p = 0; p < 8; p++) {
        float2 a2 = unpack2(accA[p]);
        float2 t2 = unpack2(accT[p]);
        bool ma = a2.x > 0.f, mb2 = a2.y > 0.f;
        float gva = g_scratch[(size_t)(b0 + 2 * p)     * NB + H1 + j];
        float gvb = g_scratch[(size_t)(b0 + 2 * p + 1) * NB + H1 + j];
        pr[2 * p]     = ma  ? t2.x * uj : 0.f;
        pr[2 * p + 1] = mb2 ? t2.y * uj : 0.f;
        gh2s[j][2 * p]     = ma  ? gva : 0.f;
        gh2s[j][2 * p + 1] = mb2 ? gvb : 0.f;
    }
    __syncthreads();

    int i0 = tid, i1 = tid + 128;
    ull gA2[8], gB2[8];
    #pragma unroll
    for (int p = 0; p < 8; p++) { gA2[p] = 0ull; gB2[p] = 0ull; }
    #pragma unroll 4
    for (int jj = 0; jj < H2; jj++) {
        ull w0 = dup2(g_W2T[jj * H1 + i0]);
        ull w1 = dup2(g_W2T[jj * H1 + i1]);
        const ull* gp = (const ull*)&gh2s[jj][0];
        #pragma unroll
        for (int p = 0; p < 8; p++) { fma2(gA2[p], w0, gp[p]); fma2(gB2[p], w1, gp[p]); }
    }
    float wi0 = g_w[i0], wi1 = g_w[i1];
    #pragma unroll
    for (int p = 0; p < 8; p++) {
        float2 ga = unpack2(gA2[p]);
        float2 gb = unpack2(gB2[p]);
        float jt0 = 0.f, jt1 = 0.f;
        if (h1s[i0][2 * p] > 0.f)     jt0 += ga.x * wi0;
        if (h1s[i1][2 * p] > 0.f)     jt0 += gb.x * wi1;
        if (h1s[i0][2 * p + 1] > 0.f) jt1 += ga.y * wi0;
        if (h1s[i1][2 * p + 1] > 0.f) jt1 += gb.y * wi1;
        pr[2 * p]     -= jt0;
        pr[2 * p + 1] -= jt1;
    }

    int lane = tid & 31, wpi = tid >> 5;
    #pragma unroll
    for (int s = 0; s < 16; s++) {
        float v = pr[s];
        #pragma unroll
        for (int off = 16; off > 0; off >>= 1)
            v += __shfl_xor_sync(0xffffffffu, v, off);
        if (lane == 0) wsum[wpi][s] = v;
    }
    __syncthreads();
    if (tid < 16) {
        out[b0 + tid] = wsum[0][tid] + wsum[1][tid] + wsum[2][tid] + wsum[3][tid] + bp[0];
    }
}

// ============================================================
// launch
// ============================================================
extern "C" void kernel_launch(void* const* d_in, const int* in_sizes, int n_in,
                              void* d_out, int out_size) {
    const float* x  = (const float*)d_in[0];
    const float* W1 = (const float*)d_in[1];
    const float* b1 = (const float*)d_in[2];
    const float* W2 = (const float*)d_in[3];
    const float* b2 = (const float*)d_in[4];
    const float* Wo = (const float*)d_in[5];
    const float* Wp = (const float*)d_in[7];
    const float* bp = (const float*)d_in[8];

    int B = in_sizes[0] / D_DIM;   // 8192

    cudaFuncSetAttribute(gemm_a1, cudaFuncAttributeMaxDynamicSharedMemorySize, A_SMEM);
    cudaFuncSetAttribute(gemm_g2, cudaFuncAttributeMaxDynamicSharedMemorySize, G_SMEM);

    prep_xT<<<dim3(64, 256), 256>>>(x);
    prep_misc<<<288, 256>>>(W1, W2, Wo, Wp);
    reduce_w_kernel<<<1, 256>>>();

    gemm_a1<<<dim3(B / AM, 4), 128, A_SMEM>>>(W1, b1);
    gemm_g2<<<B / BM, 128, G_SMEM>>>(x);

    epilogue_kernel<<<B / 16, 128>>>(b1, W2, b2, bp, (float*)d_out);
}

// round 9
// speedup vs baseline: 1.8168x; 1.1837x over previous
#include <cuda_runtime.h>
#include <cuda_bf16.h>
#include <cstdint>

typedef unsigned long long ull;

#define D_DIM 2048
#define H1 256
#define H2 128
#define NB  384
#define MAX_B 8192

static constexpr size_t B_PLANE = (size_t)NB * D_DIM;

// ---------------- device scratch ----------------
__device__ uint16_t g_Bbf[3 * B_PLANE];            // bf16 planes; rows 256..383 (Wo) used
__device__ float    g_scratch[(size_t)MAX_B * NB]; // [a1(256) | g2(128)]
__device__ float    g_u[H2];
__device__ float    g_w[H1];
__device__ float    g_wpart[16][H1];
__device__ float    g_W2T[H2 * H1];

// ---------------- helpers ----------------
__device__ __forceinline__ ull dup2(float x) {
    ull r; asm("mov.b64 %0, {%1, %1};" : "=l"(r) : "f"(x)); return r;
}
__device__ __forceinline__ void fma2(ull &d, ull a, ull b) {
    asm("fma.rn.f32x2 %0, %1, %2, %0;" : "+l"(d) : "l"(a), "l"(b));
}
__device__ __forceinline__ float2 unpack2(ull v) {
    float2 f; asm("mov.b64 {%0, %1}, %2;" : "=f"(f.x), "=f"(f.y) : "l"(v)); return f;
}
__device__ __forceinline__ void cpa16(uint32_t dst, const void* src) {
    asm volatile("cp.async.cg.shared.global [%0], [%1], 16;\n" :: "r"(dst), "l"(src));
}
__device__ __forceinline__ uint32_t s2u(const void* p) {
    uint32_t r; asm("{ .reg .u64 t; cvta.to.shared.u64 t, %1; cvt.u32.u64 %0, t; }" : "=r"(r) : "l"(p)); return r;
}
__device__ __forceinline__ uint32_t packbf(float hi, float lo) {
    uint32_t r; asm("cvt.rn.bf16x2.f32 %0, %1, %2;" : "=r"(r) : "f"(hi), "f"(lo)); return r;
}
__device__ __forceinline__ float bfhi(uint32_t v) { return __uint_as_float(v & 0xFFFF0000u); }
__device__ __forceinline__ float bflo(uint32_t v) { return __uint_as_float(v << 16); }

__device__ __forceinline__ void split3(float a, float b, uint32_t &h, uint32_t &m, uint32_t &l) {
    h = packbf(b, a);
    float ra = a - bflo(h), rb = b - bfhi(h);
    m = packbf(rb, ra);
    float sa = ra - bflo(m), sb = rb - bfhi(m);
    l = packbf(sb, sa);
}

__device__ __forceinline__ void mma16(float* c, const uint2* A, uint2 b) {
    asm volatile(
        "mma.sync.aligned.m16n8k16.row.col.f32.bf16.bf16.f32 "
        "{%0,%1,%2,%3}, {%4,%5,%6,%7}, {%8,%9}, {%0,%1,%2,%3};"
        : "+f"(c[0]), "+f"(c[1]), "+f"(c[2]), "+f"(c[3])
        : "r"(A[0].x), "r"(A[1].x), "r"(A[0].y), "r"(A[1].y), "r"(b.x), "r"(b.y));
}

// ============================================================
// prep_misc: u = Wo@Wp (bk<128), wpart (bk<144), W2T (bk<160),
//            Wo bf16 planes (bk 160..287). grid 288 x 256
// ============================================================
__global__ __launch_bounds__(256) void prep_misc(
    const float* __restrict__ W1, const float* __restrict__ W2,
    const float* __restrict__ Wo, const float* __restrict__ Wp)
{
    __shared__ float red[256];
    int tid = threadIdx.x, bk = blockIdx.x;
    if (bk < 128) {
        float s = 0.f;
        #pragma unroll 4
        for (int d = tid; d < D_DIM; d += 256)
            s += Wo[bk * D_DIM + d] * Wp[d];
        red[tid] = s; __syncthreads();
        for (int off = 128; off > 0; off >>= 1) {
            if (tid < off) red[tid] += red[tid + off];
            __syncthreads();
        }
        if (tid == 0) g_u[bk] = red[0];
    } else if (bk < 144) {
        int c = bk - 128;
        float s = 0.f;
        #pragma unroll 4
        for (int q = 0; q < 128; q++) {
            int d = c * 128 + q;
            s += W1[(long long)d * H1 + tid] * Wp[d];
        }
        g_wpart[c][tid] = s;
    } else if (bk < 160) {
        int base = (bk - 144) * 2048;
        for (int e = base + tid; e < base + 2048; e += 256) {
            int i = e >> 7, jq = e & 127;
            g_W2T[jq * H1 + i] = W2[e];
        }
    } else {
        size_t i = ((size_t)(bk - 160) * 256 + tid) * 8;   // Wo [128 x 2048]
        float4 v0 = *(const float4*)(Wo + i);
        float4 v1 = *(const float4*)(Wo + i + 4);
        uint32_t h[4], m[4], l[4];
        split3(v0.x, v0.y, h[0], m[0], l[0]);
        split3(v0.z, v0.w, h[1], m[1], l[1]);
        split3(v1.x, v1.y, h[2], m[2], l[2]);
        split3(v1.z, v1.w, h[3], m[3], l[3]);
        size_t off = (size_t)256 * D_DIM + i;
        *(uint4*)(g_Bbf + off)               = make_uint4(h[0], h[1], h[2], h[3]);
        *(uint4*)(g_Bbf + B_PLANE + off)     = make_uint4(m[0], m[1], m[2], m[3]);
        *(uint4*)(g_Bbf + 2 * B_PLANE + off) = make_uint4(l[0], l[1], l[2], l[3]);
    }
}

__global__ void reduce_w_kernel() {
    int i = threadIdx.x;
    float s = 0.f;
    #pragma unroll
    for (int c = 0; c < 16; c++) s += g_wpart[c][i];
    g_w[i] = s;
}

// ============================================================
// gemm_a1: a1[m][n] = sum_k x[m][k] W1[k][n] + b1[n]
//   FFMA2, single fp32 accumulator per output, k strictly ascending
//   (rounding chain bit-identical to all passing kernels).
//   A loaded DIRECTLY from row-major x into [m][k] smem, 80B row pitch
//   (conflict-free lds128 across lanes). 4-k register blocking.
//   CTA 128m x 64n, 128 thr (4 warps: 64m x 32n), thread rows
//   wm + h*32 + 8b + r. grid (64, 4) = 256 CTAs.
// ============================================================
#define AM 128
#define AN 64
#define AK 16
static constexpr int A_PITCH = 80;                    // bytes per A smem row
static constexpr int A_BOFF  = AM * A_PITCH;          // 10240
static constexpr int A_STG_B = A_BOFF + AN * AK * 4;  // 14336
static constexpr int A_SMEM  = 4 * A_STG_B;           // 57344

__device__ __forceinline__ void a1_load(uint32_t sb, int s, const float* __restrict__ X,
                                        const float* __restrict__ W1,
                                        int m0, int n0, int k0, int tid) {
    uint32_t base = sb + s * A_STG_B;
    #pragma unroll
    for (int q = 0; q < 4; q++) {        // A: 128 rows x 16k = 512 x 16B
        int idx = q * 128 + tid;
        int row = idx >> 2, seg = idx & 3;
        cpa16(base + row * A_PITCH + seg * 16,
              X + (size_t)(m0 + row) * D_DIM + k0 + seg * 4);
    }
    #pragma unroll
    for (int q = 0; q < 2; q++) {        // B: 16k x 64n = 256 x 16B
        int idx = q * 128 + tid;
        int kk = idx >> 4, seg = idx & 15;
        cpa16(base + A_BOFF + kk * 256 + seg * 16,
              W1 + (size_t)(k0 + kk) * H1 + n0 + seg * 4);
    }
    asm volatile("cp.async.commit_group;" ::: "memory");
}

__global__ __launch_bounds__(128) void gemm_a1(const float* __restrict__ X,
                                               const float* __restrict__ W1,
                                               const float* __restrict__ b1) {
    extern __shared__ char smem[];
    uint32_t sb = s2u(smem);
    int tid = threadIdx.x, wid = tid >> 5, lid = tid & 31;
    int m0 = blockIdx.x * AM, n0 = blockIdx.y * AN;
    int wm = (wid & 1) * 64, wn = (wid >> 1) * 32;
    int r = lid >> 2, cg = lid & 3;

    ull acc[2][4][4];
    #pragma unroll
    for (int h = 0; h < 2; h++)
        #pragma unroll
        for (int b = 0; b < 4; b++)
            #pragma unroll
            for (int j = 0; j < 4; j++) acc[h][b][j] = 0ull;

    a1_load(sb, 0, X, W1, m0, n0, 0,      tid);
    a1_load(sb, 1, X, W1, m0, n0, AK,     tid);
    a1_load(sb, 2, X, W1, m0, n0, 2 * AK, tid);

    const int NITER = D_DIM / AK;   // 128
    for (int i = 0; i < NITER; i++) {
        int s = i & 3;
        asm volatile("cp.async.wait_group %0;" :: "n"(2) : "memory");
        __syncthreads();
        if (i + 3 < NITER) a1_load(sb, (i + 3) & 3, X, W1, m0, n0, (i + 3) * AK, tid);
        else asm volatile("cp.async.commit_group;" ::: "memory");

        const char* stg = smem + s * A_STG_B;
        #pragma unroll
        for (int g = 0; g < 4; g++) {
            // A: one float4 = 4 ascending k for one m-row; 8 rows
            float4 av[2][4];
            #pragma unroll
            for (int h = 0; h < 2; h++)
                #pragma unroll
                for (int b = 0; b < 4; b++)
                    av[h][b] = *(const float4*)(stg + (wm + h * 32 + 8 * b + r) * A_PITCH + g * 16);
            #pragma unroll
            for (int c = 0; c < 4; c++) {        // k = i*16 + g*4 + c, ascending
                int kk = g * 4 + c;
                ulonglong2 bA = *(const ulonglong2*)(stg + A_BOFF + kk * 256 + (wn + 4 * cg) * 4);
                ulonglong2 bB = *(const ulonglong2*)(stg + A_BOFF + kk * 256 + (wn + 16 + 4 * cg) * 4);
                #pragma unroll
                for (int b = 0; b < 4; b++) {
                    ull a0 = dup2(((const float*)&av[0][b])[c]);
                    ull a1d = dup2(((const float*)&av[1][b])[c]);
                    fma2(acc[0][b][0], a0,  bA.x); fma2(acc[0][b][1], a0,  bA.y);
                    fma2(acc[0][b][2], a0,  bB.x); fma2(acc[0][b][3], a0,  bB.y);
                    fma2(acc[1][b][0], a1d, bA.x); fma2(acc[1][b][1], a1d, bA.y);
                    fma2(acc[1][b][2], a1d, bB.x); fma2(acc[1][b][3], a1d, bB.y);
                }
            }
        }
    }

    #pragma unroll
    for (int h = 0; h < 2; h++)
        #pragma unroll
        for (int b = 0; b < 4; b++) {
            size_t M = (size_t)(m0 + wm + h * 32 + 8 * b + r);
            float* dst = g_scratch + M * NB + n0 + wn;
            #pragma unroll
            for (int j = 0; j < 4; j++) {
                int nc = (j >> 1) * 16 + 4 * cg + (j & 1) * 2;
                float2 v = unpack2(acc[h][b][j]);
                v.x += b1[n0 + wn + nc];
                v.y += b1[n0 + wn + nc + 1];
                *(float2*)(dst + nc) = v;
            }
        }
}

// ============================================================
// gemm_g2: g2[m][j] = sum_k x[m][k] Wo[j][k]  (linear path)
//   bf16 6-product; A (x) loaded fp32, split3 in registers.
//   CTA 64m x 128n, 128 thr, 4-stage. grid B/64.
// ============================================================
#define BM 64
#define BN 128
#define KC 16
static constexpr int GB_OFF  = BM * KC * 4;               // 4096
static constexpr int G_STG   = GB_OFF + 3 * BN * KC * 2;  // 16384
static constexpr int G_SMEM  = 4 * G_STG;                 // 65536

__device__ __forceinline__ void g2_load(uint32_t sb, int s, const float* __restrict__ X,
                                        int m0, int k0, int tid) {
    uint32_t base = sb + s * G_STG;
    #pragma unroll
    for (int q = 0; q < 2; q++) {
        int idx = q * 128 + tid;
        int row = idx >> 2, seg = idx & 3;
        cpa16(base + row * 64 + seg * 16,
              X + (size_t)(m0 + row) * D_DIM + k0 + seg * 4);
    }
    #pragma unroll
    for (int q = 0; q < 6; q++) {
        int i = q * 128 + tid;
        int plane = i >> 8, rem = i & 255, row = rem >> 1, half = rem & 1;
        cpa16(base + GB_OFF + plane * 4096 + row * 32 + half * 16,
              g_Bbf + (size_t)plane * B_PLANE + (size_t)(256 + row) * D_DIM + k0 + half * 8);
    }
    asm volatile("cp.async.commit_group;" ::: "memory");
}

__global__ __launch_bounds__(128) void gemm_g2(const float* __restrict__ X) {
    extern __shared__ char smem[];
    uint32_t sb = s2u(smem);
    int tid = threadIdx.x, wid = tid >> 5, lid = tid & 31;
    int m0 = blockIdx.x * BM;
    int warp_m = (wid & 1) * 32, warp_n = (wid >> 1) * 64;
    int rr = lid >> 2, cc = lid & 3;

    float c[2][8][4];
    #pragma unroll
    for (int mf = 0; mf < 2; mf++)
        #pragma unroll
        for (int nf = 0; nf < 8; nf++)
            #pragma unroll
            for (int q = 0; q < 4; q++) c[mf][nf][q] = 0.f;

    g2_load(sb, 0, X, m0, 0,      tid);
    g2_load(sb, 1, X, m0, KC,     tid);
    g2_load(sb, 2, X, m0, 2 * KC, tid);

    const int NITER = D_DIM / KC;
    for (int i = 0; i < NITER; i++) {
        int s = i & 3;
        asm volatile("cp.async.wait_group %0;" :: "n"(2) : "memory");
        __syncthreads();
        if (i + 3 < NITER) g2_load(sb, (i + 3) & 3, X, m0, (i + 3) * KC, tid);
        else asm volatile("cp.async.commit_group;" ::: "memory");

        const char* stg = smem + s * G_STG;

        uint2 Af[3][2][2];
        #pragma unroll
        for (int mf = 0; mf < 2; mf++)
            #pragma unroll
            for (int j = 0; j < 2; j++) {
                float4 v = *(const float4*)(stg + (warp_m + mf * 16 + j * 8 + rr) * 64 + cc * 16);
                uint32_t h0, m0_, l0, h1, m1_, l1;
                split3(v.x, v.y, h0, m0_, l0);
                split3(v.z, v.w, h1, m1_, l1);
                Af[0][mf][j] = make_uint2(h0, h1);
                Af[1][mf][j] = make_uint2(m0_, m1_);
                Af[2][mf][j] = make_uint2(l0, l1);
            }

        #pragma unroll
        for (int hh = 0; hh < 2; hh++) {
            uint2 Bf[3][4];
            #pragma unroll
            for (int p = 0; p < 3; p++)
                #pragma unroll
                for (int nf = 0; nf < 4; nf++)
                    Bf[p][nf] = *(const uint2*)(stg + GB_OFF + p * 4096 +
                                                (warp_n + (hh * 4 + nf) * 8 + rr) * 32 + cc * 8);
            #pragma unroll
            for (int nf = 0; nf < 4; nf++) {
                int nn = hh * 4 + nf;
                #pragma unroll
                for (int mf = 0; mf < 2; mf++) {
                    float* cp = c[mf][nn];
                    mma16(cp, Af[0][mf], Bf[0][nf]);
                    mma16(cp, Af[0][mf], Bf[1][nf]);
                    mma16(cp, Af[1][mf], Bf[0][nf]);
                    mma16(cp, Af[1][mf], Bf[1][nf]);
                    mma16(cp, Af[0][mf], Bf[2][nf]);
                    mma16(cp, Af[2][mf], Bf[0][nf]);
                }
            }
        }
    }

    #pragma unroll
    for (int mf = 0; mf < 2; mf++) {
        int mA = m0 + warp_m + mf * 16 + rr;
        #pragma unroll
        for (int nf = 0; nf < 8; nf++) {
            int n = 256 + warp_n + nf * 8 + 2 * cc;
            float2 v0 = { c[mf][nf][0], c[mf][nf][1] };
            float2 v1 = { c[mf][nf][2], c[mf][nf][3] };
            *(float2*)&g_scratch[(size_t)mA * NB + n]       = v0;
            *(float2*)&g_scratch[(size_t)(mA + 8) * NB + n] = v1;
        }
    }
}

// ============================================================
// Epilogue: 16 samples/block, 128 threads (chains identical to passing kernel)
// ============================================================
__global__ __launch_bounds__(128) void epilogue_kernel(
    const float* __restrict__ b1, const float* __restrict__ W2,
    const float* __restrict__ b2, const float* __restrict__ bp,
    float* __restrict__ out)
{
    __shared__ float h1s[H1][16];
    __shared__ float th1s[H1][16];
    __shared__ float gh2s[H2][16];
    __shared__ float wsum[4][16];

    int tid = threadIdx.x;
    int b0  = blockIdx.x * 16;

    for (int idx = tid; idx < 16 * H1; idx += 128) {
        int s = idx >> 8, i = idx & 255;
        float a = g_scratch[(size_t)(b0 + s) * NB + i];
        bool m = a > 0.f;
        h1s[i][s]  = m ? a : 0.f;
        th1s[i][s] = m ? (a - b1[i]) : 0.f;
    }
    __syncthreads();

    int j = tid;
    ull accA[8], accT[8];
    ull bd = dup2(b2[j]);
    #pragma unroll
    for (int p = 0; p < 8; p++) { accA[p] = bd; accT[p] = 0ull; }
    #pragma unroll 4
    for (int i = 0; i < H1; i++) {
        ull wd = dup2(W2[i * H2 + j]);
        const ull* hp = (const ull*)&h1s[i][0];
        const ull* tp = (const ull*)&th1s[i][0];
        #pragma unroll
        for (int p = 0; p < 8; p++) { fma2(accA[p], wd, hp[p]); fma2(accT[p], wd, tp[p]); }
    }
    float pr[16];
    float uj = g_u[j];
    #pragma unroll
    for (int p = 0; p < 8; p++) {
        float2 a2 = unpack2(accA[p]);
        float2 t2 = unpack2(accT[p]);
        bool ma = a2.x > 0.f, mb2 = a2.y > 0.f;
        float gva = g_scratch[(size_t)(b0 + 2 * p)     * NB + H1 + j];
        float gvb = g_scratch[(size_t)(b0 + 2 * p + 1) * NB + H1 + j];
        pr[2 * p]     = ma  ? t2.x * uj : 0.f;
        pr[2 * p + 1] = mb2 ? t2.y * uj : 0.f;
        gh2s[j][2 * p]     = ma  ? gva : 0.f;
        gh2s[j][2 * p + 1] = mb2 ? gvb : 0.f;
    }
    __syncthreads();

    int i0 = tid, i1 = tid + 128;
    ull gA2[8], gB2[8];
    #pragma unroll
    for (int p = 0; p < 8; p++) { gA2[p] = 0ull; gB2[p] = 0ull; }
    #pragma unroll 4
    for (int jj = 0; jj < H2; jj++) {
        ull w0 = dup2(g_W2T[jj * H1 + i0]);
        ull w1 = dup2(g_W2T[jj * H1 + i1]);
        const ull* gp = (const ull*)&gh2s[jj][0];
        #pragma unroll
        for (int p = 0; p < 8; p++) { fma2(gA2[p], w0, gp[p]); fma2(gB2[p], w1, gp[p]); }
    }
    float wi0 = g_w[i0], wi1 = g_w[i1];
    #pragma unroll
    for (int p = 0; p < 8; p++) {
        float2 ga = unpack2(gA2[p]);
        float2 gb = unpack2(gB2[p]);
        float jt0 = 0.f, jt1 = 0.f;
        if (h1s[i0][2 * p] > 0.f)     jt0 += ga.x * wi0;
        if (h1s[i1][2 * p] > 0.f)     jt0 += gb.x * wi1;
        if (h1s[i0][2 * p + 1] > 0.f) jt1 += ga.y * wi0;
        if (h1s[i1][2 * p + 1] > 0.f) jt1 += gb.y * wi1;
        pr[2 * p]     -= jt0;
        pr[2 * p + 1] -= jt1;
    }

    int lane = tid & 31, wpi = tid >> 5;
    #pragma unroll
    for (int s = 0; s < 16; s++) {
        float v = pr[s];
        #pragma unroll
        for (int off = 16; off > 0; off >>= 1)
            v += __shfl_xor_sync(0xffffffffu, v, off);
        if (lane == 0) wsum[wpi][s] = v;
    }
    __syncthreads();
    if (tid < 16) {
        out[b0 + tid] = wsum[0][tid] + wsum[1][tid] + wsum[2][tid] + wsum[3][tid] + bp[0];
    }
}

// ============================================================
// launch — fork/join: a1 on side stream (no prep deps), preps+g2 on main
// ============================================================
extern "C" void kernel_launch(void* const* d_in, const int* in_sizes, int n_in,
                              void* d_out, int out_size) {
    const float* x  = (const float*)d_in[0];
    const float* W1 = (const float*)d_in[1];
    const float* b1 = (const float*)d_in[2];
    const float* W2 = (const float*)d_in[3];
    const float* b2 = (const float*)d_in[4];
    const float* Wo = (const float*)d_in[5];
    const float* Wp = (const float*)d_in[7];
    const float* bp = (const float*)d_in[8];

    int B = in_sizes[0] / D_DIM;   // 8192

    static cudaStream_t s_side = nullptr;
    static cudaEvent_t ev_fork = nullptr, ev_join = nullptr;
    if (s_side == nullptr) {
        cudaStreamCreateWithFlags(&s_side, cudaStreamNonBlocking);
        cudaEventCreateWithFlags(&ev_fork, cudaEventDisableTiming);
        cudaEventCreateWithFlags(&ev_join, cudaEventDisableTiming);
        cudaFuncSetAttribute(gemm_a1, cudaFuncAttributeMaxDynamicSharedMemorySize, A_SMEM);
        cudaFuncSetAttribute(gemm_g2, cudaFuncAttributeMaxDynamicSharedMemorySize, G_SMEM);
    }

    // fork: a1 depends only on x, W1, b1
    cudaEventRecord(ev_fork, 0);
    cudaStreamWaitEvent(s_side, ev_fork, 0);
    gemm_a1<<<dim3(B / AM, 4), 128, A_SMEM, s_side>>>(x, W1, b1);

    // main: preps then g2 (needs g_Bbf)
    prep_misc<<<288, 256>>>(W1, W2, Wo, Wp);
    reduce_w_kernel<<<1, 256>>>();
    gemm_g2<<<B / BM, 128, G_SMEM>>>(x);

    // join, then epilogue (needs both scratch halves)
    cudaEventRecord(ev_join, s_side);
    cudaStreamWaitEvent(0, ev_join, 0);
    epilogue_kernel<<<B / 16, 128>>>(b1, W2, b2, bp, (float*)d_out);
}